// round 1
// baseline (speedup 1.0000x reference)
#include <cuda_runtime.h>
#include <cstdint>

// ---------------------------------------------------------------------------
// Idefics3VisionEmbeddings:
//   out[b, p, d] = sum_k pixel_patch(b,p)[k] * conv_w[d][k] + conv_b[d]
//                  + pos_emb[position_id(b,p)][d]
// GEMM: M=21632 (=32*676), N=1152, K=588 (=3*14*14). All tile-exact.
// ---------------------------------------------------------------------------

namespace {
constexpr int kNPS   = 26;
constexpr int kPatch = 14;
constexpr int kB     = 32;
constexpr int kC     = 3;
constexpr int kHW    = 364;
constexpr int kD     = 1152;
constexpr int kP     = kNPS * kNPS;            // 676
constexpr int kK     = kC * kPatch * kPatch;   // 588
constexpr int kM     = kB * kP;                // 21632

constexpr int BM = 128, BN = 128, BK = 14;
constexpr int TM = 8, TN = 8;
constexpr int NTHREADS = 256;
constexpr int KT = kK / BK;                    // 42
}  // namespace

// Scratch for position ids (no cudaMalloc allowed).
__device__ int g_pos[kB * kP];

// ---------------------------------------------------------------------------
// Position-id kernel: replicates the reference fp32 math exactly.
//   boundaries[j] = (j+1)/26 (fp32 div)
//   frac = (p / nb) * (1 - 1e-6)   (fp32 div then mul)
//   id = #{ j : boundaries[j] <= frac }  (searchsorted side='right')
// Mask dtype auto-detect: byte 1 nonzero  => u8/bool layout (nb_w >= 13
// guarantees mask[0][0][1] == 1); byte 1 == 0 => int32 layout.
// ---------------------------------------------------------------------------
__global__ void pos_kernel(const unsigned char* __restrict__ mraw) {
    const int b = blockIdx.x;
    const int t = threadIdx.x;

    __shared__ int s_bh[kNPS];
    __shared__ int s_bw[kNPS];
    __shared__ int s_nbh, s_nbw;

    const bool is_u8 = (mraw[1] != 0);
    // element accessor for mask[b, i, j]
    auto mval = [&](int idx) -> int {
        return is_u8 ? (int)mraw[idx] : (int)mraw[4 * (size_t)idx];
    };
    const int base = b * kP;

    if (t == 0) {
        int nh = 0, nw = 0;
        for (int i = 0; i < kNPS; i++) nh += (mval(base + i * kNPS) != 0);
        for (int j = 0; j < kNPS; j++) nw += (mval(base + j) != 0);
        s_nbh = nh;
        s_nbw = nw;
    }
    __syncthreads();

    if (t < kNPS) {
        const float eps = 1.0f - 1e-6f;
        const float fh = ((float)t / (float)s_nbh) * eps;
        const float fw = ((float)t / (float)s_nbw) * eps;
        int ch = 0, cw = 0;
        #pragma unroll
        for (int j = 1; j < kNPS; j++) {
            const float bnd = (float)j / (float)kNPS;
            ch += (bnd <= fh) ? 1 : 0;
            cw += (bnd <= fw) ? 1 : 0;
        }
        s_bh[t] = ch;
        s_bw[t] = cw;
    }
    __syncthreads();

    for (int p = t; p < kP; p += blockDim.x) {
        const int ph = p / kNPS;
        const int pw = p - ph * kNPS;
        const int on = (mval(base + p) != 0);
        g_pos[base + p] = on ? (s_bh[ph] * kNPS + s_bw[pw]) : 0;
    }
}

// Packed dual-FMA (sm_103a): two fp32 FMAs per instruction, exact IEEE fp32.
__device__ __forceinline__ void ffma2(float2& d, float2 a, float2 b) {
    asm("fma.rn.f32x2 %0, %1, %2, %0;"
        : "+l"(*reinterpret_cast<unsigned long long*>(&d))
        : "l"(*reinterpret_cast<unsigned long long*>(&a)),
          "l"(*reinterpret_cast<unsigned long long*>(&b)));
}

// ---------------------------------------------------------------------------
// Implicit-GEMM patch-embed with fused bias + positional-embedding epilogue.
// Grid: (169, 9). Block: 256 threads, 8x8 microtile each.
// BK = 14 so each A-tile K-slice is 14 contiguous floats of one pixel row.
// ---------------------------------------------------------------------------
__global__ __launch_bounds__(NTHREADS, 2)
void gemm_kernel(const float* __restrict__ pix,
                 const float* __restrict__ wgt,
                 const float* __restrict__ bias,
                 const float* __restrict__ pe,
                 float* __restrict__ out) {
    __shared__ float As[BK][BM];
    __shared__ float Bs[BK][BN];

    const int tid = threadIdx.x;
    const int bm  = blockIdx.x;
    const int bn  = blockIdx.y;

    const int tx = tid & 15;
    const int ty = tid >> 4;

    // Tile-load mapping: 2 threads per row, each loads 7 contiguous floats.
    const int lrow = tid >> 1;          // 0..127
    const int lk   = (tid & 1) * 7;     // 0 or 7

    // A (im2col) source address for this thread's row.
    const int m   = bm * BM + lrow;
    const int b   = m / kP;
    const int rem = m - b * kP;
    const int ph  = rem / kNPS;
    const int pw  = rem - ph * kNPS;
    const float* apix = pix + (size_t)b * (kC * kHW * kHW)
                        + (ph * kPatch) * kHW + pw * kPatch + lk;

    // B (weights) source row.
    const int n = bn * BN + lrow;
    const float* wrow = wgt + (size_t)n * kK + lk;

    float2 acc[TM][TN / 2];
    #pragma unroll
    for (int i = 0; i < TM; i++)
        #pragma unroll
        for (int j = 0; j < TN / 2; j++) acc[i][j] = make_float2(0.f, 0.f);

    #pragma unroll 1
    for (int kt = 0; kt < KT; kt++) {
        const int c  = kt / kPatch;          // channel
        const int ky = kt - c * kPatch;      // row within patch
        const float* ap = apix + c * (kHW * kHW) + ky * kHW;
        const float* bp = wrow + kt * BK;

        float ar[7], br[7];
        #pragma unroll
        for (int i = 0; i < 7; i++) {
            ar[i] = ap[i];
            br[i] = bp[i];
        }
        __syncthreads();  // previous tile's compute done
        #pragma unroll
        for (int i = 0; i < 7; i++) {
            As[lk + i][lrow] = ar[i];
            Bs[lk + i][lrow] = br[i];
        }
        __syncthreads();  // tile visible

        #pragma unroll
        for (int kk = 0; kk < BK; kk++) {
            const float4 a0 = *reinterpret_cast<const float4*>(&As[kk][ty * TM]);
            const float4 a1 = *reinterpret_cast<const float4*>(&As[kk][ty * TM + 4]);
            const float4 b0 = *reinterpret_cast<const float4*>(&Bs[kk][tx * TN]);
            const float4 b1 = *reinterpret_cast<const float4*>(&Bs[kk][tx * TN + 4]);
            const float aa[8] = {a0.x, a0.y, a0.z, a0.w, a1.x, a1.y, a1.z, a1.w};
            float2 bb[4];
            bb[0] = make_float2(b0.x, b0.y);
            bb[1] = make_float2(b0.z, b0.w);
            bb[2] = make_float2(b1.x, b1.y);
            bb[3] = make_float2(b1.z, b1.w);
            #pragma unroll
            for (int i = 0; i < TM; i++) {
                const float2 ad = make_float2(aa[i], aa[i]);
                #pragma unroll
                for (int j = 0; j < TN / 2; j++) ffma2(acc[i][j], ad, bb[j]);
            }
        }
    }

    // Epilogue: + conv_b + pos_emb[position_id]
    const int mbase = bm * BM + ty * TM;
    const int nbase = bn * BN + tx * TN;
    #pragma unroll
    for (int i = 0; i < TM; i++) {
        const int mm  = mbase + i;
        const int pos = g_pos[mm];
        const float* per = pe + (size_t)pos * kD + nbase;
        float* orow = out + (size_t)mm * kD + nbase;
        #pragma unroll
        for (int j = 0; j < TN / 2; j++) {
            float2 v = acc[i][j];
            v.x += per[2 * j]     + bias[nbase + 2 * j];
            v.y += per[2 * j + 1] + bias[nbase + 2 * j + 1];
            *reinterpret_cast<float2*>(&orow[2 * j]) = v;
        }
    }
}

extern "C" void kernel_launch(void* const* d_in, const int* in_sizes, int n_in,
                              void* d_out, int out_size) {
    const float* pix          = (const float*)d_in[0];
    const unsigned char* mask = (const unsigned char*)d_in[1];
    const float* wgt          = (const float*)d_in[2];
    const float* bias         = (const float*)d_in[3];
    const float* pe           = (const float*)d_in[4];
    float* out                = (float*)d_out;

    pos_kernel<<<kB, 128>>>(mask);

    dim3 grid(kM / BM, kD / BN);  // (169, 9)
    gemm_kernel<<<grid, NTHREADS>>>(pix, wgt, bias, pe, out);
}